// round 9
// baseline (speedup 1.0000x reference)
#include <cuda_runtime.h>
#include <cuda_fp16.h>
#include <cstdint>

#define NSENT 4000
#define LSEQ  128
#define EMBD  60
#define HID   230
#define HIDP  232
#define NBAG  500
#define NREL  25
#define GRID  148

#define ESW2   36        // es row stride in half2 words (conflict-free LDSM)
#define NCH    264       // padded channels (halves per B k-row)
#define WROWW  132       // B k-row stride in 4B words (132 mod 32 = 4 -> LDSM conflict-free)
#define WKROWS 192       // 3 taps x 64 padded k

// ---- smem layout (4-byte words) ----
#define W_WORDS  (WKROWS * WROWW)          // 25344
#define ES_WORDS (130 * ESW2)              // 4680
#define OFF_ES0  (W_WORDS)
#define OFF_ES1  (W_WORDS + ES_WORDS)
#define OFF_WBUF (W_WORDS + 2 * ES_WORDS)  // 2 bufs x 8 warps x 240 floats
#define SM_DYN   ((OFF_WBUF + 2 * 8 * 240) * 4)

__device__ __align__(16) float g_h[NSENT * HIDP];

#define MMAH(c, a, b0, b1)                                                  \
    asm volatile("mma.sync.aligned.m16n8k16.row.col.f32.f16.f16.f32 "       \
        "{%0,%1,%2,%3}, {%4,%5,%6,%7}, {%8,%9}, {%0,%1,%2,%3};"             \
        : "+f"((c)[0]), "+f"((c)[1]), "+f"((c)[2]), "+f"((c)[3])            \
        : "r"((a)[0]), "r"((a)[1]), "r"((a)[2]), "r"((a)[3]),               \
          "r"(b0), "r"(b1))

#define LDSM4(d, addr)                                                       \
    asm volatile("ldmatrix.sync.aligned.m8n8.x4.shared.b16 {%0,%1,%2,%3}, [%4];" \
        : "=r"((d)[0]), "=r"((d)[1]), "=r"((d)[2]), "=r"((d)[3]) : "r"(addr))

#define LDSM4T(d, addr)                                                      \
    asm volatile("ldmatrix.sync.aligned.m8n8.x4.trans.shared.b16 {%0,%1,%2,%3}, [%4];" \
        : "=r"((d)[0]), "=r"((d)[1]), "=r"((d)[2]), "=r"((d)[3]) : "r"(addr))

__device__ __forceinline__ uint32_t smem_u32(const void* p) {
    uint32_t a;
    asm("{ .reg .u64 t; cvta.to.shared.u64 t, %1; cvt.u32.u64 %0, t; }" : "=r"(a) : "l"(p));
    return a;
}

// ---------------------------------------------------------------------------
// Persistent fused conv: gather + conv1d(k=3) + maxpool + relu, fp16 mma
// grid=148, block=256. Warp w owns m16 rows [16w,16w+16) x 29 n-tiles (exact 232),
// processed in two n-passes (tiles 0..15, 16..28) with reg-double-buffered B.
// ---------------------------------------------------------------------------
__global__ __launch_bounds__(256, 1) void conv_mma_kernel(
    const int*   __restrict__ X,
    const int*   __restrict__ P1,
    const int*   __restrict__ P2,
    const float* __restrict__ WE,
    const float* __restrict__ E1,
    const float* __restrict__ E2,
    const float* __restrict__ conv_w,
    const float* __restrict__ conv_b)
{
    extern __shared__ uint32_t sm[];
    const uint32_t sb = smem_u32(sm);
    __half* wH  = (__half*)sm;                  // [192][264] halves
    float* wbuf = (float*)(sm + OFF_WBUF);      // [2 buf][8 warp][240]

    const int tid  = threadIdx.x;
    const int lane = tid & 31;
    const int warp = tid >> 5;
    const int l4   = lane & 3;

    // ---- one-time: zero W region + both es buffers; stage weights ----
    for (int i = tid; i < W_WORDS + 2 * ES_WORDS; i += 256) sm[i] = 0u;
    __syncthreads();
    for (int i = tid; i < HID * 180; i += 256) {
        int c = i / 180, j = i - c * 180;
        int k = j / 3, tap = j - k * 3;
        wH[(tap * 64 + k) * NCH + c] = __float2half(conv_w[i]);
    }

    // ---- gather (thread t: row l = t>>1, half = t&1, 30 emb values) ----
    const int gl   = tid >> 1;
    const int half = tid & 1;
    float v[30];

    auto prefetch = [&](int n) {
        int x = X[n * LSEQ + gl];
        if (half == 0) {
            const float* w = WE + x * 50;
            #pragma unroll
            for (int j = 0; j < 30; j++) v[j] = w[j];
        } else {
            const float* w = WE + x * 50 + 30;
            #pragma unroll
            for (int j = 0; j < 20; j++) v[j] = w[j];
            int p1 = P1[n * LSEQ + gl];
            int p2 = P2[n * LSEQ + gl];
            const float* e1 = E1 + p1 * 5;
            const float* e2 = E2 + p2 * 5;
            #pragma unroll
            for (int j = 0; j < 5; j++) v[20 + j] = e1[j];
            #pragma unroll
            for (int j = 0; j < 5; j++) v[25 + j] = e2[j];
        }
    };
    auto sts_emb = [&](int esoff) {
        uint32_t* dst = sm + esoff + (gl + 1) * ESW2 + half * 15;
        #pragma unroll
        for (int j = 0; j < 15; j++) {
            __half2 h = __floats2half2_rn(v[2 * j], v[2 * j + 1]);
            dst[j] = *(uint32_t*)&h;
        }
    };

    // ---- per-lane LDSM address components ----
    const int a_row  = warp * 16 + (lane & 15);     // + t per tap
    const int a_ksel = (lane >> 4) * 4;
    const int b_krow = (lane & 15);
    const int b_nsel = (lane >> 4) * 4;

    const int n0 = blockIdx.x;
    prefetch(n0);
    __syncthreads();
    sts_emb(OFF_ES0);
    __syncthreads();

    int cur = 0;
    for (int n = n0; n < NSENT; n += GRID) {
        const int nn = n + GRID;
        if (nn < NSENT) prefetch(nn);          // LDGs fly under the MMAs

        const int esoff = cur ? OFF_ES1 : OFF_ES0;
        float* wb = wbuf + (cur * 8 + warp) * 240;

        // ---- two n-passes: pass0 pr 0..7 (nt 0..15), pass1 pr 8..14 (nt 16..28)
        #pragma unroll 1
        for (int pass = 0; pass < 2; pass++) {
            const int pr0  = pass ? 8 : 0;
            const int prN  = pass ? 7 : 8;      // #pairs this pass
            const int ntN  = pass ? 13 : 16;    // #tiles this pass

            float acc[16][4];
            #pragma unroll
            for (int j = 0; j < 16; j++)
                #pragma unroll
                for (int q = 0; q < 4; q++) acc[j][q] = 0.f;

            #pragma unroll 1
            for (int t = 0; t < 3; t++) {
                #pragma unroll
                for (int ks = 0; ks < 4; ks++) {
                    uint32_t a[4];
                    uint32_t ad = sb + ((esoff + (a_row + t) * ESW2
                                         + ks * 8 + a_ksel) << 2);
                    LDSM4(a, ad);
                    const int krow0 = t * 64 + ks * 16 + b_krow;
                    const uint32_t bbase = sb + ((krow0 * WROWW + b_nsel) << 2);

                    uint32_t bc[4], bn[4];
                    LDSM4T(bc, bbase + (pr0 * 8 << 2));
                    #pragma unroll
                    for (int p = 0; p < 8; p++) {
                        if (p >= prN) break;
                        if (p + 1 < prN) LDSM4T(bn, bbase + ((pr0 + p + 1) * 8 << 2));
                        MMAH(acc[2 * p], a, bc[0], bc[1]);
                        if (2 * p + 1 < ntN) MMAH(acc[2 * p + 1], a, bc[2], bc[3]);
                        #pragma unroll
                        for (int q = 0; q < 4; q++) bc[q] = bn[q];
                    }
                }
            }

            // epilogue for this pass: max over warp's 16 rows -> wbuf
            #pragma unroll
            for (int j = 0; j < 16; j++) {
                if (j >= ntN) break;
                const int nt = 2 * pr0 + j;
                float m0 = fmaxf(acc[j][0], acc[j][2]);
                float m1 = fmaxf(acc[j][1], acc[j][3]);
                #pragma unroll
                for (int off = 4; off < 32; off <<= 1) {
                    m0 = fmaxf(m0, __shfl_xor_sync(0xffffffffu, m0, off));
                    m1 = fmaxf(m1, __shfl_xor_sync(0xffffffffu, m1, off));
                }
                if (lane < 4) {
                    wb[nt * 8 + 2 * l4]     = m0;
                    wb[nt * 8 + 2 * l4 + 1] = m1;
                }
            }
        }

        if (nn < NSENT) sts_emb(cur ? OFF_ES0 : OFF_ES1);
        __syncthreads();          // wbuf + next es visible

        if (tid < HIDP) {
            const float* w0 = wbuf + cur * 8 * 240;
            float m = w0[tid];
            #pragma unroll
            for (int w = 1; w < 8; w++) m = fmaxf(m, w0[w * 240 + tid]);
            float b = (tid < HID) ? conv_b[tid] : 0.f;
            g_h[n * HIDP + tid] = fmaxf(m + b, 0.f);
        }
        cur ^= 1;
    }
}

// ---------------------------------------------------------------------------
// Per-bag attention pooling + classifier (float4 on g_h rows)
// ---------------------------------------------------------------------------
__global__ __launch_bounds__(256) void bag_kernel(
    const int*   __restrict__ scope,
    const int*   __restrict__ relation,
    const float* __restrict__ rel_w,
    const float* __restrict__ rel_b,
    float*       __restrict__ out)
{
    __shared__ float q[HIDP];      // padded with zeros
    __shared__ float rep[HIDP];
    __shared__ float logit[8];
    __shared__ float alpha[8];

    const int b   = blockIdx.x;
    const int rel = relation[b];
    const int s0  = scope[2 * b];
    int ns        = scope[2 * b + 1] - s0;
    if (ns > 8) ns = 8;

    for (int t = threadIdx.x; t < HIDP; t += 256)
        q[t] = (t < HID) ? rel_w[rel * HID + t] : 0.f;
    __syncthreads();

    const int lane = threadIdx.x & 31;
    const int warp = threadIdx.x >> 5;

    {   // logits: warp s computes dot(h[s0+s], q) with float4 loads
        float p = 0.f;
        if (warp < ns) {
            const float4* hr = (const float4*)(g_h + (size_t)(s0 + warp) * HIDP);
            const float4* q4 = (const float4*)q;
            #pragma unroll
            for (int c = lane; c < HIDP / 4; c += 32) {
                float4 hv = hr[c], qv = q4[c];
                p += hv.x * qv.x + hv.y * qv.y + hv.z * qv.z + hv.w * qv.w;
            }
        }
        #pragma unroll
        for (int off = 16; off; off >>= 1) p += __shfl_xor_sync(0xffffffffu, p, off);
        if (lane == 0 && warp < 8) logit[warp] = (warp < ns) ? p : -1e30f;
    }
    __syncthreads();

    if (threadIdx.x == 0) {
        float m = -1e30f;
        for (int s = 0; s < ns; s++) m = fmaxf(m, logit[s]);
        float den = 0.f;
        for (int s = 0; s < ns; s++) { float e = expf(logit[s] - m); alpha[s] = e; den += e; }
        float inv = 1.f / den;
        for (int s = 0; s < ns; s++) alpha[s] *= inv;
    }
    __syncthreads();

    // bag_rep = sum_s alpha[s] * h[s0+s]  (float4)
    for (int t = threadIdx.x; t < HIDP / 4; t += 256) {
        float4 r = make_float4(0.f, 0.f, 0.f, 0.f);
        for (int s = 0; s < ns; s++) {
            float4 hv = ((const float4*)(g_h + (size_t)(s0 + s) * HIDP))[t];
            float a = alpha[s];
            r.x = fmaf(a, hv.x, r.x);
            r.y = fmaf(a, hv.y, r.y);
            r.z = fmaf(a, hv.z, r.z);
            r.w = fmaf(a, hv.w, r.w);
        }
        ((float4*)rep)[t] = r;
    }
    __syncthreads();

    for (int r = warp; r < NREL; r += 8) {
        float p = 0.f;
        const float* wr = rel_w + r * HID;
        for (int c = lane; c < HID; c += 32) p += rep[c] * wr[c];
        #pragma unroll
        for (int off = 16; off; off >>= 1) p += __shfl_xor_sync(0xffffffffu, p, off);
        if (lane == 0) out[b * NREL + r] = p + rel_b[r];
    }
}

// ---------------------------------------------------------------------------
extern "C" void kernel_launch(void* const* d_in, const int* in_sizes, int n_in,
                              void* d_out, int out_size)
{
    const int*   X        = (const int*)d_in[0];
    const int*   P1       = (const int*)d_in[1];
    const int*   P2       = (const int*)d_in[2];
    const int*   scope    = (const int*)d_in[5];
    const int*   relation = (const int*)d_in[6];
    const float* WE       = (const float*)d_in[7];
    const float* E1       = (const float*)d_in[8];
    const float* E2       = (const float*)d_in[9];
    const float* conv_w   = (const float*)d_in[10];
    const float* conv_b   = (const float*)d_in[11];
    const float* rel_w    = (const float*)d_in[12];
    const float* rel_b    = (const float*)d_in[13];
    float*       out      = (float*)d_out;

    cudaFuncSetAttribute(conv_mma_kernel,
                         cudaFuncAttributeMaxDynamicSharedMemorySize, SM_DYN);

    conv_mma_kernel<<<GRID, 256, SM_DYN>>>(X, P1, P2, WE, E1, E2, conv_w, conv_b);
    bag_kernel<<<NBAG, 256>>>(scope, relation, rel_w, rel_b, out);
}

// round 13
// speedup vs baseline: 1.2046x; 1.2046x over previous
#include <cuda_runtime.h>
#include <cuda_fp16.h>
#include <cstdint>

#define NSENT 4000
#define LSEQ  128
#define EMBD  60
#define HID   230
#define HIDP  232
#define NBAG  500
#define NREL  25
#define GRID  148

#define ESW2   36                 // es row stride in half2 words (conflict-free LDSM)
#define NCH    264                // padded channels (halves per B k-row)
#define WROWW  132                // B k-row stride in 4B words (132 mod 32 = 4 -> conflict-free)
#define WKROWS 192                // 3 taps x 64 padded k

// ---- smem layout (4-byte words) ----
#define W_WORDS  (WKROWS * WROWW)          // 25344
#define ES_WORDS (130 * ESW2)              // 4680
#define OFF_ES0  (W_WORDS)
#define OFF_ES1  (W_WORDS + ES_WORDS)
#define OFF_WBUF (W_WORDS + 2 * ES_WORDS)  // 2 bufs x 2 mg x 264 floats
#define SM_DYN   ((OFF_WBUF + 2 * 2 * NCH) * 4)

__device__ __align__(16) float g_h[NSENT * HIDP];

#define MMAH(c, a, b0, b1)                                                  \
    asm volatile("mma.sync.aligned.m16n8k16.row.col.f32.f16.f16.f32 "       \
        "{%0,%1,%2,%3}, {%4,%5,%6,%7}, {%8,%9}, {%0,%1,%2,%3};"             \
        : "+f"((c)[0]), "+f"((c)[1]), "+f"((c)[2]), "+f"((c)[3])            \
        : "r"((a)[0]), "r"((a)[1]), "r"((a)[2]), "r"((a)[3]),               \
          "r"(b0), "r"(b1))

#define LDSM4(d, addr)                                                       \
    asm volatile("ldmatrix.sync.aligned.m8n8.x4.shared.b16 {%0,%1,%2,%3}, [%4];" \
        : "=r"((d)[0]), "=r"((d)[1]), "=r"((d)[2]), "=r"((d)[3]) : "r"(addr))

#define LDSM4T(d, addr)                                                      \
    asm volatile("ldmatrix.sync.aligned.m8n8.x4.trans.shared.b16 {%0,%1,%2,%3}, [%4];" \
        : "=r"((d)[0]), "=r"((d)[1]), "=r"((d)[2]), "=r"((d)[3]) : "r"(addr))

__device__ __forceinline__ uint32_t smem_u32(const void* p) {
    uint32_t a;
    asm("{ .reg .u64 t; cvta.to.shared.u64 t, %1; cvt.u32.u64 %0, t; }" : "=r"(a) : "l"(p));
    return a;
}

// ---------------------------------------------------------------------------
// Persistent fused conv: gather + conv1d(k=3) + maxpool + relu, fp16 mma + ldmatrix
// grid=148, block=256 (8 warps: 2 m-groups x 4 n-groups; warp tile 64x64)
// == R6 mainloop (best measured) with weight-prep folded in ==
// ---------------------------------------------------------------------------
__global__ __launch_bounds__(256, 1) void conv_mma_kernel(
    const int*   __restrict__ X,
    const int*   __restrict__ P1,
    const int*   __restrict__ P2,
    const float* __restrict__ WE,
    const float* __restrict__ E1,
    const float* __restrict__ E2,
    const float* __restrict__ conv_w,
    const float* __restrict__ conv_b)
{
    extern __shared__ uint32_t sm[];
    const uint32_t sb = smem_u32(sm);
    __half* wH  = (__half*)sm;                 // [192][264] halves
    float* wbuf = (float*)(sm + OFF_WBUF);     // [2 buf][2 mg][264]

    const int tid  = threadIdx.x;
    const int lane = tid & 31;
    const int warp = tid >> 5;
    const int mg   = warp >> 2;
    const int ng   = warp & 3;
    const int l4   = lane & 3;
    const int lu   = lane >> 2;

    // ---- one-time: zero W + es buffers, then scatter conv_w -> wH (fp16) ----
    for (int i = tid; i < W_WORDS + 2 * ES_WORDS; i += 256) sm[i] = 0u;
    __syncthreads();
    for (int i = tid; i < HID * 180; i += 256) {
        int c = i / 180, j = i - c * 180;
        int k = j / 3, tap = j - k * 3;
        wH[(tap * 64 + k) * NCH + c] = __float2half(conv_w[i]);
    }

    // ---- gather (thread t: row l = t>>1, half = t&1, 30 emb values) ----
    const int gl   = tid >> 1;
    const int half = tid & 1;
    float v[30];

    auto prefetch = [&](int n) {
        int x = X[n * LSEQ + gl];
        if (half == 0) {
            const float* w = WE + x * 50;
            #pragma unroll
            for (int j = 0; j < 30; j++) v[j] = w[j];
        } else {
            const float* w = WE + x * 50 + 30;
            #pragma unroll
            for (int j = 0; j < 20; j++) v[j] = w[j];
            int p1 = P1[n * LSEQ + gl];
            int p2 = P2[n * LSEQ + gl];
            const float* e1 = E1 + p1 * 5;
            const float* e2 = E2 + p2 * 5;
            #pragma unroll
            for (int j = 0; j < 5; j++) v[20 + j] = e1[j];
            #pragma unroll
            for (int j = 0; j < 5; j++) v[25 + j] = e2[j];
        }
    };
    auto sts_emb = [&](int esoff) {
        uint32_t* dst = sm + esoff + (gl + 1) * ESW2 + half * 15;
        #pragma unroll
        for (int j = 0; j < 15; j++) {
            __half2 h = __floats2half2_rn(v[2 * j], v[2 * j + 1]);
            dst[j] = *(uint32_t*)&h;
        }
    };

    // ---- per-lane LDSM address components ----
    const int a_row  = mg * 64 + (lane & 15);      // + t + mt*16
    const int a_ksel = (lane >> 4) * 4;            // k-half offset in words
    const int b_krow = (lane & 15);                // k row within kstep
    const int b_nsel = (lane >> 4) * 4;            // channel-half offset in words
    const int b_chw  = ng * 32;                    // channel base in words

    const int n0 = blockIdx.x;
    prefetch(n0);
    __syncthreads();              // weights + zeros visible
    sts_emb(OFF_ES0);
    __syncthreads();              // first sentence staged

    int cur = 0;
    for (int n = n0; n < NSENT; n += GRID) {
        const int nn = n + GRID;
        if (nn < NSENT) prefetch(nn);          // LDGs fly under the MMAs

        const int esoff = cur ? OFF_ES1 : OFF_ES0;

        float acc[4][8][4];
        #pragma unroll
        for (int mt = 0; mt < 4; mt++)
            #pragma unroll
            for (int nt = 0; nt < 8; nt++)
                #pragma unroll
                for (int q = 0; q < 4; q++) acc[mt][nt][q] = 0.f;

        #pragma unroll 1
        for (int t = 0; t < 3; t++) {
            #pragma unroll
            for (int ks = 0; ks < 4; ks++) {
                uint32_t a[4][4];
                #pragma unroll
                for (int mt = 0; mt < 4; mt++) {
                    uint32_t ad = sb + ((esoff + (a_row + t + mt * 16) * ESW2
                                         + ks * 8 + a_ksel) << 2);
                    LDSM4(a[mt], ad);
                }
                const int krow0 = t * 64 + ks * 16 + b_krow;
                #pragma unroll
                for (int pr = 0; pr < 4; pr++) {
                    uint32_t b[4];
                    uint32_t bd = sb + ((krow0 * WROWW + b_chw + pr * 8 + b_nsel) << 2);
                    LDSM4T(b, bd);
                    #pragma unroll
                    for (int mt = 0; mt < 4; mt++) {
                        MMAH(acc[mt][2 * pr],     a[mt], b[0], b[1]);
                        MMAH(acc[mt][2 * pr + 1], a[mt], b[2], b[3]);
                    }
                }
            }
        }

        // ---- epilogue: max over rows -> wbuf[cur]; stage next sentence ----
        float* wb = wbuf + cur * 2 * NCH;
        #pragma unroll
        for (int nt = 0; nt < 8; nt++) {
            float m0 = -1e30f, m1 = -1e30f;
            #pragma unroll
            for (int mt = 0; mt < 4; mt++) {
                m0 = fmaxf(m0, fmaxf(acc[mt][nt][0], acc[mt][nt][2]));
                m1 = fmaxf(m1, fmaxf(acc[mt][nt][1], acc[mt][nt][3]));
            }
            #pragma unroll
            for (int off = 4; off < 32; off <<= 1) {
                m0 = fmaxf(m0, __shfl_xor_sync(0xffffffffu, m0, off));
                m1 = fmaxf(m1, __shfl_xor_sync(0xffffffffu, m1, off));
            }
            if (lu == 0) {
                int c = ng * 64 + nt * 8 + l4 * 2;
                wb[mg * NCH + c]     = m0;
                wb[mg * NCH + c + 1] = m1;
            }
        }
        if (nn < NSENT) sts_emb(cur ? OFF_ES0 : OFF_ES1);
        __syncthreads();          // wbuf[cur] + es[next] visible to all

        if (tid < HIDP) {
            float m = fmaxf(wb[tid], wb[NCH + tid]);
            float b = (tid < HID) ? conv_b[tid] : 0.f;
            g_h[n * HIDP + tid] = fmaxf(m + b, 0.f);
        }
        cur ^= 1;                 // next MMA block reads es[next]; wbuf ping-pongs
    }
}

// ---------------------------------------------------------------------------
// Per-bag attention pooling + classifier (float4 on g_h rows)
// ---------------------------------------------------------------------------
__global__ __launch_bounds__(256) void bag_kernel(
    const int*   __restrict__ scope,
    const int*   __restrict__ relation,
    const float* __restrict__ rel_w,
    const float* __restrict__ rel_b,
    float*       __restrict__ out)
{
    __shared__ float q[HIDP];      // padded with zeros
    __shared__ float rep[HIDP];
    __shared__ float logit[8];
    __shared__ float alpha[8];

    const int b   = blockIdx.x;
    const int rel = relation[b];
    const int s0  = scope[2 * b];
    int ns        = scope[2 * b + 1] - s0;
    if (ns > 8) ns = 8;

    for (int t = threadIdx.x; t < HIDP; t += 256)
        q[t] = (t < HID) ? rel_w[rel * HID + t] : 0.f;
    __syncthreads();

    const int lane = threadIdx.x & 31;
    const int warp = threadIdx.x >> 5;

    {   // logits: warp s computes dot(h[s0+s], q) with float4 loads
        float p = 0.f;
        if (warp < ns) {
            const float4* hr = (const float4*)(g_h + (size_t)(s0 + warp) * HIDP);
            const float4* q4 = (const float4*)q;
            #pragma unroll
            for (int c = lane; c < HIDP / 4; c += 32) {
                float4 hv = hr[c], qv = q4[c];
                p += hv.x * qv.x + hv.y * qv.y + hv.z * qv.z + hv.w * qv.w;
            }
        }
        #pragma unroll
        for (int off = 16; off; off >>= 1) p += __shfl_xor_sync(0xffffffffu, p, off);
        if (lane == 0 && warp < 8) logit[warp] = (warp < ns) ? p : -1e30f;
    }
    __syncthreads();

    if (threadIdx.x == 0) {
        float m = -1e30f;
        for (int s = 0; s < ns; s++) m = fmaxf(m, logit[s]);
        float den = 0.f;
        for (int s = 0; s < ns; s++) { float e = expf(logit[s] - m); alpha[s] = e; den += e; }
        float inv = 1.f / den;
        for (int s = 0; s < ns; s++) alpha[s] *= inv;
    }
    __syncthreads();

    // bag_rep = sum_s alpha[s] * h[s0+s]  (float4)
    for (int t = threadIdx.x; t < HIDP / 4; t += 256) {
        float4 r = make_float4(0.f, 0.f, 0.f, 0.f);
        for (int s = 0; s < ns; s++) {
            float4 hv = ((const float4*)(g_h + (size_t)(s0 + s) * HIDP))[t];
            float a = alpha[s];
            r.x = fmaf(a, hv.x, r.x);
            r.y = fmaf(a, hv.y, r.y);
            r.z = fmaf(a, hv.z, r.z);
            r.w = fmaf(a, hv.w, r.w);
        }
        ((float4*)rep)[t] = r;
    }
    __syncthreads();

    for (int r = warp; r < NREL; r += 8) {
        float p = 0.f;
        const float* wr = rel_w + r * HID;
        for (int c = lane; c < HID; c += 32) p += rep[c] * wr[c];
        #pragma unroll
        for (int off = 16; off; off >>= 1) p += __shfl_xor_sync(0xffffffffu, p, off);
        if (lane == 0) out[b * NREL + r] = p + rel_b[r];
    }
}

// ---------------------------------------------------------------------------
extern "C" void kernel_launch(void* const* d_in, const int* in_sizes, int n_in,
                              void* d_out, int out_size)
{
    const int*   X        = (const int*)d_in[0];
    const int*   P1       = (const int*)d_in[1];
    const int*   P2       = (const int*)d_in[2];
    const int*   scope    = (const int*)d_in[5];
    const int*   relation = (const int*)d_in[6];
    const float* WE       = (const float*)d_in[7];
    const float* E1       = (const float*)d_in[8];
    const float* E2       = (const float*)d_in[9];
    const float* conv_w   = (const float*)d_in[10];
    const float* conv_b   = (const float*)d_in[11];
    const float* rel_w    = (const float*)d_in[12];
    const float* rel_b    = (const float*)d_in[13];
    float*       out      = (float*)d_out;

    cudaFuncSetAttribute(conv_mma_kernel,
                         cudaFuncAttributeMaxDynamicSharedMemorySize, SM_DYN);

    conv_mma_kernel<<<GRID, 256, SM_DYN>>>(X, P1, P2, WE, E1, E2, conv_w, conv_b);
    bag_kernel<<<NBAG, 256>>>(scope, relation, rel_w, rel_b, out);
}